// round 9
// baseline (speedup 1.0000x reference)
#include <cuda_runtime.h>
#include <cuda_fp16.h>
#include <cstdint>

#define BB 16
#define NN 16384
#define CC 128
#define KK 9
#define TM 128
#define THREADS 512
#define NCHUNK_CONV 72          // 8 c8-slices * 9 ko, K=16 each
#define NCHUNK 80               // + 8 skip chunks
#define CHUNK_GB 4096
#define ROW_SB 48               // smem row stride: 32B data + 16B pad
#define BUF_B (128 * ROW_SB)    // 6144
#define NWBUF 4

// smem layout (bytes)
#define WBUF_OFF 0                          // 4 * 6144
#define ABUF_OFF (NWBUF * BUF_B)            // 24576 (+2*6144)
#define P2_OFF   (ABUF_OFF + 2 * BUF_B)     // 36864
#define IDX_OFF  (P2_OFF + 128 * 108 * 4)   // 92160
#define BIAS_OFF (IDX_OFF + 128 * KK * 4)   // 96768
#define SMEM_TOTAL (BIAS_OFF + 1024)        // 97792

// barrier ids (0 reserved for __syncthreads)
#define BID_FULL0  1
#define BID_FULL1  2
#define BID_EMPTY0 3
#define BID_EMPTY1 4

__device__ __align__(16) __half g_Wc[NCHUNK_CONV * 2048];
__device__ __align__(16) __half g_Ws[8 * 2048];

__host__ __device__ __forceinline__ int perm16(int p) {
    int e = p & 1;
    return (p < 8) ? ((p >> 1) * 4 + e) : (((p - 8) >> 1) * 4 + 2 + e);
}

__global__ void prep_w(const float* __restrict__ Wc, const float* __restrict__ Ws) {
    int t = blockIdx.x * blockDim.x + threadIdx.x;
    if (t < NCHUNK_CONV * 2048) {
        int qn = t >> 11, r = t & 2047, o = r >> 4, p = r & 15;
        int c8 = qn / 9, ko = qn % 9;
        g_Wc[t] = __float2half_rn(Wc[o * 1152 + ko * CC + c8 * 16 + perm16(p)]);
    }
    if (t < 8 * 2048) {
        int qn = t >> 11, r = t & 2047, o = r >> 4, p = r & 15;
        g_Ws[t] = __float2half_rn(Ws[o * CC + qn * 16 + perm16(p)]);
    }
}

// ---------------- PTX helpers ----------------
__device__ __forceinline__ uint32_t smem_u32(const void* p) {
    uint32_t a;
    asm("{ .reg .u64 t; cvta.to.shared.u64 t, %1; cvt.u32.u64 %0, t; }" : "=r"(a) : "l"(p));
    return a;
}
__device__ __forceinline__ void bar_sync(int id) {
    asm volatile("bar.sync %0, %1;" :: "r"(id), "r"(THREADS) : "memory");
}
__device__ __forceinline__ void bar_arrive(int id) {
    asm volatile("bar.arrive %0, %1;" :: "r"(id), "r"(THREADS) : "memory");
}
#define CP_ASYNC16(dst, src) \
    asm volatile("cp.async.cg.shared.global [%0], [%1], 16;" :: "r"(dst), "l"(src))
#define CP_COMMIT() asm volatile("cp.async.commit_group;" ::: "memory")
#define CP_WAIT(n)  asm volatile("cp.async.wait_group %0;" :: "n"(n) : "memory")

__device__ __forceinline__ void ldsm_x4(uint32_t* r, uint32_t addr) {
    asm volatile("ldmatrix.sync.aligned.m8n8.x4.shared.b16 {%0,%1,%2,%3}, [%4];"
                 : "=r"(r[0]), "=r"(r[1]), "=r"(r[2]), "=r"(r[3]) : "r"(addr));
}
__device__ __forceinline__ void mma16816(float* c, const uint32_t* a,
                                         uint32_t b0, uint32_t b1) {
    asm volatile("mma.sync.aligned.m16n8k16.row.col.f32.f16.f16.f32 "
                 "{%0,%1,%2,%3}, {%4,%5,%6,%7}, {%8,%9}, {%0,%1,%2,%3};"
                 : "+f"(c[0]), "+f"(c[1]), "+f"(c[2]), "+f"(c[3])
                 : "r"(a[0]), "r"(a[1]), "r"(a[2]), "r"(a[3]), "r"(b0), "r"(b1));
}
__device__ __forceinline__ float elu(float v) {
    float e;
    asm("ex2.approx.f32 %0, %1;" : "=f"(e) : "f"(v * 1.44269504f));
    return v > 0.f ? v : e - 1.f;
}
__device__ __forceinline__ void fma4(float4& a, float s, const float4& v) {
    a.x = fmaf(s, v.x, a.x); a.y = fmaf(s, v.y, a.y);
    a.z = fmaf(s, v.z, a.z); a.w = fmaf(s, v.w, a.w);
}
__device__ __forceinline__ uint32_t h2pack(float a, float b) {
    __half2 h = __floats2half2_rn(a, b);
    return *reinterpret_cast<uint32_t*>(&h);
}
#define STS_V2(addr, r0, r1) \
    asm volatile("st.shared.v2.b32 [%0], {%1,%2};" :: "r"(addr), "r"(r0), "r"(r1) : "memory")

// consumer-side chunk fetch: 256 consumer threads, 16B each
__device__ __forceinline__ void issue_chunk(uint32_t wbase, int i, int ctid) {
    const char* src = (i < NCHUNK_CONV)
        ? (const char*)g_Wc + (size_t)i * CHUNK_GB
        : (const char*)g_Ws + (size_t)(i - NCHUNK_CONV) * CHUNK_GB;
    int o = ctid >> 1, h = ctid & 1;
    uint32_t dst = wbase + (i & (NWBUF - 1)) * BUF_B + o * ROW_SB + h * 16;
    CP_ASYNC16(dst, src + o * 32 + h * 16);
    CP_COMMIT();
}

__global__ __launch_bounds__(THREADS, 1)
void paiconv_ws(const float* __restrict__ x, const int* __restrict__ idxg,
                const float* __restrict__ P, const float* __restrict__ b_conv,
                const float* __restrict__ b_skip, float* __restrict__ out)
{
    extern __shared__ char smem[];
    const uint32_t sb = smem_u32(smem);
    const int tid  = threadIdx.x;
    const int lane = tid & 31;
    const int n0   = blockIdx.x * TM;
    const int b    = blockIdx.y;

    float* s_P2   = (float*)(smem + P2_OFF);     // [node][ko][12]
    int*   s_idx  = (int*)(smem + IDX_OFF);
    float* s_bias = (float*)(smem + BIAS_OFF);

    // consumers start the W pipeline
    if (tid >= 256) {
        int ctid = tid - 256;
        issue_chunk(sb + WBUF_OFF, 0, ctid);
        issue_chunk(sb + WBUF_OFF, 1, ctid);
        issue_chunk(sb + WBUF_OFF, 2, ctid);
    }

    for (int t = tid; t < TM * 81; t += THREADS) {
        int node = t / 81, rem = t - node * 81;
        int ko = rem / 9, j = rem - ko * 9;
        s_P2[node * 108 + ko * 12 + j] = P[(size_t)n0 * 81 + t];
    }
    for (int t = tid; t < TM * KK; t += THREADS) s_idx[t] = idxg[n0 * KK + t];
    if (tid < CC)       s_bias[tid] = b_conv[tid];
    else if (tid < 256) s_bias[tid] = b_skip[tid - CC];
    __syncthreads();

    const float* xb = x + (size_t)b * NN * CC;

    if (tid < 256) {
        // ================= PRODUCER: gather + mix + ELU -> A chunks =================
        // handshake: arrive(FULL) after write; sync(EMPTY) before overwrite
        const int row = tid >> 1;            // node 0..127
        const int qh  = tid & 1;             // channel half: 8*qh..8*qh+7
        const uint32_t a_st = sb + ABUF_OFF + row * ROW_SB + qh * 8;

        uint32_t noff[KK];
        #pragma unroll
        for (int j = 0; j < KK; j++) {
            unsigned ix = (unsigned)s_idx[row * KK + j];
            noff[j] = (ix < (unsigned)NN) ? ix * 512u : 0xFFFFFFFFu;
        }

        int ci = 0;
        for (int c8 = 0; c8 < 8; c8++) {
            float4 xg0[KK], xg1[KK];
            #pragma unroll
            for (int j = 0; j < KK; j++) {
                float4 v0 = make_float4(0.f, 0.f, 0.f, 0.f);
                float4 v1 = v0;
                if (noff[j] != 0xFFFFFFFFu) {
                    const char* srcp = (const char*)xb + (size_t)noff[j] + c8 * 64 + qh * 32;
                    v0 = __ldg((const float4*)srcp);
                    v1 = __ldg((const float4*)(srcp + 16));
                }
                xg0[j] = v0; xg1[j] = v1;
            }
            #pragma unroll
            for (int ko = 0; ko < 9; ko++, ci++) {
                if (ci >= 2) bar_sync((ci & 1) ? BID_EMPTY1 : BID_EMPTY0);

                const float* p = s_P2 + row * 108 + ko * 12;
                float4 pa = *(const float4*)p, pb = *(const float4*)(p + 4);
                float p8 = p[8];
                float4 v0 = make_float4(0.f, 0.f, 0.f, 0.f);
                float4 v1 = v0;
                fma4(v0, pa.x, xg0[0]); fma4(v1, pa.x, xg1[0]);
                fma4(v0, pa.y, xg0[1]); fma4(v1, pa.y, xg1[1]);
                fma4(v0, pa.z, xg0[2]); fma4(v1, pa.z, xg1[2]);
                fma4(v0, pa.w, xg0[3]); fma4(v1, pa.w, xg1[3]);
                fma4(v0, pb.x, xg0[4]); fma4(v1, pb.x, xg1[4]);
                fma4(v0, pb.y, xg0[5]); fma4(v1, pb.y, xg1[5]);
                fma4(v0, pb.z, xg0[6]); fma4(v1, pb.z, xg1[6]);
                fma4(v0, pb.w, xg0[7]); fma4(v1, pb.w, xg1[7]);
                fma4(v0, p8,   xg0[8]); fma4(v1, p8,   xg1[8]);

                uint32_t ha0 = h2pack(elu(v0.x), elu(v0.y));
                uint32_t ha1 = h2pack(elu(v1.x), elu(v1.y));
                uint32_t hb0 = h2pack(elu(v0.z), elu(v0.w));
                uint32_t hb1 = h2pack(elu(v1.z), elu(v1.w));
                uint32_t ad = a_st + (ci & 1) * BUF_B;
                STS_V2(ad, ha0, ha1);
                STS_V2(ad + 16, hb0, hb1);

                bar_arrive((ci & 1) ? BID_FULL1 : BID_FULL0);
            }
        }
        // skip chunks: A = x (fp16)
        for (int c8 = 0; c8 < 8; c8++, ci++) {
            if (ci >= 2) bar_sync((ci & 1) ? BID_EMPTY1 : BID_EMPTY0);
            const char* srcp = (const char*)xb + (size_t)(n0 + row) * 512 + c8 * 64 + qh * 32;
            float4 v0 = __ldg((const float4*)srcp);
            float4 v1 = __ldg((const float4*)(srcp + 16));
            uint32_t ad = a_st + (ci & 1) * BUF_B;
            STS_V2(ad,      h2pack(v0.x, v0.y), h2pack(v1.x, v1.y));
            STS_V2(ad + 16, h2pack(v0.z, v0.w), h2pack(v1.z, v1.w));
            bar_arrive((ci & 1) ? BID_FULL1 : BID_FULL0);
        }
    } else {
        // ================= CONSUMER: ldsm + HMMA =================
        // handshake: sync(FULL) before read; arrive(EMPTY) after read
        const int ctid = tid - 256;
        const int cw   = ctid >> 5;              // 0..7
        const int mrow = (cw >> 1) * 32;
        const int ncol = (cw & 1) * 64;
        const uint32_t a_l0 = sb + ABUF_OFF + (mrow + (lane & 15)) * ROW_SB + (lane >> 4) * 16;
        const uint32_t b_l0 = sb + WBUF_OFF + (ncol + (lane & 15)) * ROW_SB + (lane >> 4) * 16;

        float acc[64];
        #pragma unroll
        for (int i = 0; i < 64; i++) acc[i] = 0.f;

        for (int ci = 0; ci < NCHUNK; ci++) {
            bar_sync((ci & 1) ? BID_FULL1 : BID_FULL0);
            if (ci + 3 < NCHUNK) issue_chunk(sb + WBUF_OFF, ci + 3, ctid);
            if (ci < NCHUNK - 2) { CP_WAIT(2); }
            else if (ci == NCHUNK - 2) { CP_WAIT(1); }
            else { CP_WAIT(0); }

            // fold conv accs before first skip chunk's MMAs
            if (ci == NCHUNK_CONV) {
                const int cb = (lane & 3) * 2;
                #pragma unroll
                for (int ai = 0; ai < 2; ai++)
                    #pragma unroll
                    for (int g = 0; g < 4; g++) {
                        float* a = acc + (ai * 4 + g) * 8;
                        int c0 = ncol + g * 16 + cb;
                        float2 bc0 = *(const float2*)(s_bias + c0);
                        float2 bs0 = *(const float2*)(s_bias + 128 + c0);
                        float2 bc1 = *(const float2*)(s_bias + c0 + 8);
                        float2 bs1 = *(const float2*)(s_bias + 128 + c0 + 8);
                        a[0] = elu(a[0] + bc0.x) + bs0.x;
                        a[1] = elu(a[1] + bc0.y) + bs0.y;
                        a[2] = elu(a[2] + bc0.x) + bs0.x;
                        a[3] = elu(a[3] + bc0.y) + bs0.y;
                        a[4] = elu(a[4] + bc1.x) + bs1.x;
                        a[5] = elu(a[5] + bc1.y) + bs1.y;
                        a[6] = elu(a[6] + bc1.x) + bs1.x;
                        a[7] = elu(a[7] + bc1.y) + bs1.y;
                    }
            }

            const uint32_t ab = a_l0 + (ci & 1) * BUF_B;
            const uint32_t wb = b_l0 + (ci & 3) * BUF_B;
            uint32_t a0[4], a1[4];
            ldsm_x4(a0, ab);
            ldsm_x4(a1, ab + 16 * ROW_SB);
            #pragma unroll
            for (int g = 0; g < 4; g++) {
                uint32_t bf[4];
                ldsm_x4(bf, wb + g * 16 * ROW_SB);
                mma16816(acc + (0 * 4 + g) * 8,     a0, bf[0], bf[2]);
                mma16816(acc + (0 * 4 + g) * 8 + 4, a0, bf[1], bf[3]);
                mma16816(acc + (1 * 4 + g) * 8,     a1, bf[0], bf[2]);
                mma16816(acc + (1 * 4 + g) * 8 + 4, a1, bf[1], bf[3]);
            }
            if (ci <= NCHUNK - 3) bar_arrive((ci & 1) ? BID_EMPTY1 : BID_EMPTY0);
        }

        // epilogue: store (conv fold at ci==72; skip folded via accumulation)
        const int cb = (lane & 3) * 2;
        #pragma unroll
        for (int ai = 0; ai < 2; ai++)
            #pragma unroll
            for (int h = 0; h < 2; h++) {
                int r = mrow + ai * 16 + (lane >> 2) + h * 8;
                float* orow = out + ((size_t)b * NN + n0 + r) * CC;
                #pragma unroll
                for (int g = 0; g < 4; g++) {
                    float* a = acc + (ai * 4 + g) * 8;
                    *(float2*)(orow + ncol + g * 16 + cb)     = make_float2(a[h * 2],     a[h * 2 + 1]);
                    *(float2*)(orow + ncol + g * 16 + 8 + cb) = make_float2(a[4 + h * 2], a[4 + h * 2 + 1]);
                }
            }
    }
}

extern "C" void kernel_launch(void* const* d_in, const int* in_sizes, int n_in,
                              void* d_out, int out_size) {
    const float* x       = (const float*)d_in[0];
    const int*   indices = (const int*)  d_in[1];
    const float* P       = (const float*)d_in[2];
    const float* W_conv  = (const float*)d_in[3];
    const float* b_conv  = (const float*)d_in[4];
    const float* W_skip  = (const float*)d_in[5];
    const float* b_skip  = (const float*)d_in[6];
    float* out = (float*)d_out;

    prep_w<<<(NCHUNK_CONV * 2048 + 255) / 256, 256>>>(W_conv, W_skip);

    cudaFuncSetAttribute(paiconv_ws,
                         cudaFuncAttributeMaxDynamicSharedMemorySize, SMEM_TOTAL);
    dim3 grid(NN / TM, BB);
    paiconv_ws<<<grid, THREADS, SMEM_TOTAL>>>(x, indices, P, b_conv, b_skip, out);
}